// round 13
// baseline (speedup 1.0000x reference)
#include <cuda_runtime.h>
#include <cuda_fp16.h>
#include <math.h>
#include <stdint.h>

// Problem constants (B,T,H,A) = (64, 2048, 1024, 256)
#define BB 64
#define TT 2048
#define HH 1024
#define AA 256
#define BT (BB*TT)          // 131072 rows
#define M_CTA 64
#define NCTA (BT/M_CTA)     // 2048 CTAs, 32 per batch
#define CPB 32              // S-partials per batch

#define KSTEP 32
#define NK (HH/KSTEP)       // 32
#define A_STRIDE 40         // halfs per A row (pad: 80B, conflict-free LDSM)
#define B_STRIDE 264        // halfs per B row (pad: 528B, conflict-free LDSM)
#define A_TILE (M_CTA*A_STRIDE)   // 2560 halfs / stage
#define B_TILE (KSTEP*B_STRIDE)   // 8448 halfs / stage

// ---------------- device scratch (no allocations allowed) ----------------
__device__ float g_S[(size_t)NCTA * HH];   // per-chunk weighted sums (8MB)
__device__ float g_m[NCTA];                // per-chunk max
__device__ float g_l[NCTA];                // per-chunk exp-sum
__device__ __align__(16) __half g_Wh[HH * AA]; // W in fp16 [H][A]

__device__ __forceinline__ uint32_t smem_u32(const void* p) {
    uint32_t a;
    asm("{ .reg .u64 t; cvta.to.shared.u64 t, %1; cvt.u32.u64 %0, t; }" : "=r"(a) : "l"(p));
    return a;
}

// =====================================================================
// K0: convert W [H,A] fp32 -> g_Wh fp16 (rn)
// =====================================================================
__global__ void convert_w_kernel(const float* __restrict__ W)
{
    const int i = (blockIdx.x * 256 + threadIdx.x) * 4;
    const float4 f = *reinterpret_cast<const float4*>(W + i);
    __half2 h0 = __floats2half2_rn(f.x, f.y);
    __half2 h1 = __floats2half2_rn(f.z, f.w);
    *reinterpret_cast<uint2*>(g_Wh + i) =
        make_uint2(*reinterpret_cast<uint32_t*>(&h0), *reinterpret_cast<uint32_t*>(&h1));
}

// =====================================================================
// K1: fp16 mma.m16n8k16 GEMM, CTA tile 64x256, 256 threads, 2 CTAs/SM,
//     R3-proven staging (LDG->reg->STS for A and B, double buffer,
//     two syncs per k-step). Fused chunked-softmax epilogue + S-pass.
// 8 warps (2x4); warp tile 32 rows x 64 cols.
// =====================================================================
__global__ __launch_bounds__(256, 2)
void vu_fp16_kernel(const float* __restrict__ x,
                    const float* __restrict__ bo, const float* __restrict__ uo)
{
    extern __shared__ char smem[];
    __half* As = reinterpret_cast<__half*>(smem);                    // [2][A_TILE]
    __half* Bs = reinterpret_cast<__half*>(smem) + 2 * A_TILE;       // [2][B_TILE]
    __shared__ float vu_s[M_CTA];
    __shared__ float redm;

    const int tid  = threadIdx.x;
    const int lane = tid & 31;
    const int warp = tid >> 5;
    const int g    = lane >> 2;           // groupID
    const int tg   = lane & 3;            // thread-in-group
    const int wrow = (warp >> 2) * 32;    // 0,32
    const int wcol = (warp & 3) * 64;     // 0,64,128,192

    const uint32_t asBase = smem_u32(As);
    const uint32_t bsBase = smem_u32(Bs);

    const size_t row0 = (size_t)blockIdx.x * M_CTA;

    // ---- gmem staging mapping ----
    const int ar = tid >> 2;              // A row 0..63
    const int ak = (tid & 3) * 8;         // A k-sub 0,8,16,24
    const float* aPtr = x + (row0 + ar) * HH + ak;

    const int bk = tid >> 3;              // B k-row 0..31
    const int bn = (tid & 7) * 32;        // B n 0,32,...,224
    const __half* bPtr = g_Wh + (size_t)bk * AA + bn;

    float acc[2][8][4];
    #pragma unroll
    for (int mi = 0; mi < 2; mi++)
        #pragma unroll
        for (int ni = 0; ni < 8; ni++)
            #pragma unroll
            for (int c = 0; c < 4; c++) acc[mi][ni][c] = 0.f;

    __half2 aR[4];
    uint4 bR[4];

    auto ldgA = [&](int k0) {
        const float4 f0 = *reinterpret_cast<const float4*>(aPtr + k0);
        const float4 f1 = *reinterpret_cast<const float4*>(aPtr + k0 + 4);
        aR[0] = __floats2half2_rn(f0.x, f0.y);
        aR[1] = __floats2half2_rn(f0.z, f0.w);
        aR[2] = __floats2half2_rn(f1.x, f1.y);
        aR[3] = __floats2half2_rn(f1.z, f1.w);
    };
    auto ldgB = [&](int k0) {
        const uint4* p = reinterpret_cast<const uint4*>(bPtr + (size_t)k0 * AA);
        bR[0] = p[0];
        bR[1] = p[1];
        bR[2] = p[2];
        bR[3] = p[3];
    };
    auto stsAB = [&](int st) {
        *reinterpret_cast<uint4*>(As + st * A_TILE + ar * A_STRIDE + ak) =
            *reinterpret_cast<uint4*>(aR);
        uint4* bq = reinterpret_cast<uint4*>(Bs + st * B_TILE + bk * B_STRIDE + bn);
        bq[0] = bR[0];
        bq[1] = bR[1];
        bq[2] = bR[2];
        bq[3] = bR[3];
    };

    auto compute = [&](int st) {
        const uint32_t aB = asBase + st * (A_TILE * 2);
        const uint32_t bB = bsBase + st * (B_TILE * 2);
        #pragma unroll
        for (int sub = 0; sub < 2; sub++) {
            uint32_t a[2][4];
            #pragma unroll
            for (int mi = 0; mi < 2; mi++) {
                const uint32_t addr = aB +
                    ((wrow + mi * 16 + (lane & 15)) * A_STRIDE
                     + sub * 16 + (lane >> 4) * 8) * 2;
                asm volatile("ldmatrix.sync.aligned.m8n8.x4.shared.b16 "
                             "{%0,%1,%2,%3}, [%4];"
                             : "=r"(a[mi][0]), "=r"(a[mi][1]),
                               "=r"(a[mi][2]), "=r"(a[mi][3]) : "r"(addr));
            }
            #pragma unroll
            for (int nb = 0; nb < 4; nb++) {
                uint32_t b0, b1, b2, b3;
                const uint32_t addr = bB +
                    ((sub * 16 + (lane & 15)) * B_STRIDE
                     + wcol + nb * 16 + (lane >> 4) * 8) * 2;
                asm volatile("ldmatrix.sync.aligned.m8n8.x4.trans.shared.b16 "
                             "{%0,%1,%2,%3}, [%4];"
                             : "=r"(b0), "=r"(b1), "=r"(b2), "=r"(b3) : "r"(addr));
                #pragma unroll
                for (int mi = 0; mi < 2; mi++) {
                    asm volatile(
                        "mma.sync.aligned.m16n8k16.row.col.f32.f16.f16.f32 "
                        "{%0,%1,%2,%3},{%4,%5,%6,%7},{%8,%9},{%0,%1,%2,%3};"
                        : "+f"(acc[mi][nb*2][0]), "+f"(acc[mi][nb*2][1]),
                          "+f"(acc[mi][nb*2][2]), "+f"(acc[mi][nb*2][3])
                        : "r"(a[mi][0]), "r"(a[mi][1]), "r"(a[mi][2]), "r"(a[mi][3]),
                          "r"(b0), "r"(b1));
                    asm volatile(
                        "mma.sync.aligned.m16n8k16.row.col.f32.f16.f16.f32 "
                        "{%0,%1,%2,%3},{%4,%5,%6,%7},{%8,%9},{%0,%1,%2,%3};"
                        : "+f"(acc[mi][nb*2+1][0]), "+f"(acc[mi][nb*2+1][1]),
                          "+f"(acc[mi][nb*2+1][2]), "+f"(acc[mi][nb*2+1][3])
                        : "r"(a[mi][0]), "r"(a[mi][1]), "r"(a[mi][2]), "r"(a[mi][3]),
                          "r"(b2), "r"(b3));
                }
            }
        }
    };

    // ---- pipeline (R3 structure) ----
    ldgA(0); ldgB(0);
    stsAB(0);
    __syncthreads();

    for (int ks = 0; ks < NK; ks++) {
        const int cur = ks & 1;
        if (ks + 1 < NK) { ldgA((ks + 1) * KSTEP); ldgB((ks + 1) * KSTEP); }
        compute(cur);
        __syncthreads();
        if (ks + 1 < NK) {
            stsAB(cur ^ 1);
            __syncthreads();
        }
    }

    // ---- epilogue 1: vu[row] = sum_a tanh(z + b[a]) * u[a] -> vu_s ----
    if (tid < M_CTA) vu_s[tid] = 0.f;
    __syncthreads();
    #pragma unroll
    for (int mi = 0; mi < 2; mi++) {
        float s0 = 0.f, s1 = 0.f;
        #pragma unroll
        for (int ni = 0; ni < 8; ni++) {
            const int c0 = wcol + ni * 8 + 2 * tg;
            const float b0v = bo[c0], b1v = bo[c0 + 1];
            const float u0v = uo[c0], u1v = uo[c0 + 1];
            s0 += tanhf(acc[mi][ni][0] + b0v) * u0v + tanhf(acc[mi][ni][1] + b1v) * u1v;
            s1 += tanhf(acc[mi][ni][2] + b0v) * u0v + tanhf(acc[mi][ni][3] + b1v) * u1v;
        }
        s0 += __shfl_xor_sync(0xffffffffu, s0, 1);
        s0 += __shfl_xor_sync(0xffffffffu, s0, 2);
        s1 += __shfl_xor_sync(0xffffffffu, s1, 1);
        s1 += __shfl_xor_sync(0xffffffffu, s1, 2);
        if (tg == 0) {
            atomicAdd(&vu_s[wrow + mi * 16 + g],     s0);
            atomicAdd(&vu_s[wrow + mi * 16 + g + 8], s1);
        }
    }
    __syncthreads();

    // ---- epilogue 2: local softmax stats (64 rows) ----
    if (warp == 0) {
        float a = fmaxf(vu_s[lane], vu_s[lane + 32]);
        #pragma unroll
        for (int o = 16; o; o >>= 1) a = fmaxf(a, __shfl_xor_sync(0xffffffffu, a, o));
        if (lane == 0) redm = a;
    }
    __syncthreads();
    const float m = redm;
    if (tid < M_CTA) vu_s[tid] = expf(vu_s[tid] - m);   // vu_s now holds weights
    __syncthreads();
    if (warp == 0) {
        float a = vu_s[lane] + vu_s[lane + 32];
        #pragma unroll
        for (int o = 16; o; o >>= 1) a += __shfl_xor_sync(0xffffffffu, a, o);
        if (lane == 0) { g_m[blockIdx.x] = m; g_l[blockIdx.x] = a; }
    }
    __syncthreads();

    // ---- epilogue 3: S-pass, float4; 256 threads cover 1024 h-cols ----
    const float* xr = x + row0 * HH + tid * 4;
    float4 s = make_float4(0.f, 0.f, 0.f, 0.f);
    #pragma unroll 8
    for (int r = 0; r < M_CTA; r++) {
        const float w = vu_s[r];
        const float4 v = *reinterpret_cast<const float4*>(xr + (size_t)r * HH);
        s.x = fmaf(w, v.x, s.x);
        s.y = fmaf(w, v.y, s.y);
        s.z = fmaf(w, v.z, s.z);
        s.w = fmaf(w, v.w, s.w);
    }
    *(reinterpret_cast<float4*>(g_S + (size_t)blockIdx.x * HH) + tid) = s;
}

// =====================================================================
// K2: combine 32 chunk-partials per batch (exact softmax merge),
//     write out [B, H+1] with ones column. 64 CTAs x 256 threads.
// =====================================================================
__global__ __launch_bounds__(256)
void combine_kernel(float* __restrict__ out)
{
    const int b = blockIdx.x, tid = threadIdx.x;
    const int c0 = b * CPB;
    __shared__ float sm[CPB], sl[CPB];
    if (tid < CPB) { sm[tid] = g_m[c0 + tid]; sl[tid] = g_l[c0 + tid]; }
    __syncthreads();

    float M = -1e30f;
    #pragma unroll
    for (int c = 0; c < CPB; c++) M = fmaxf(M, sm[c]);
    float ec[CPB];
    float L = 0.f;
    #pragma unroll
    for (int c = 0; c < CPB; c++) {
        ec[c] = expf(sm[c] - M);
        L += ec[c] * sl[c];
    }
    const float inv = 1.f / L;

    for (int h = tid; h < HH; h += 256) {
        float s = 0.f;
        #pragma unroll
        for (int c = 0; c < CPB; c++)
            s += ec[c] * g_S[(size_t)(c0 + c) * HH + h];
        out[b * (HH + 1) + h] = s * inv;
    }
    if (tid == 0) out[b * (HH + 1) + HH] = 1.0f;
}

// ---------------------------------------------------------------------
extern "C" void kernel_launch(void* const* d_in, const int* in_sizes, int n_in,
                              void* d_out, int out_size)
{
    const float* x  = (const float*)d_in[0];   // [64,2048,1024]
    const float* W  = (const float*)d_in[1];   // [1024,256]
    const float* bo = (const float*)d_in[2];   // [256]
    const float* uo = (const float*)d_in[3];   // [256]
    float* out = (float*)d_out;                // [64,1025]

    const int DSMEM = 2 * (A_TILE + B_TILE) * 2;   // 44032 bytes per CTA
    static bool attr_done = false;
    if (!attr_done) {
        cudaFuncSetAttribute(vu_fp16_kernel,
                             cudaFuncAttributeMaxDynamicSharedMemorySize, DSMEM);
        attr_done = true;
    }

    convert_w_kernel<<<(HH * AA) / (256 * 4), 256>>>(W);
    vu_fp16_kernel<<<NCTA, 256, DSMEM>>>(x, bo, uo);
    combine_kernel<<<BB, 256>>>(out);
}

// round 14
// speedup vs baseline: 1.6056x; 1.6056x over previous
#include <cuda_runtime.h>
#include <cuda_fp16.h>
#include <math.h>
#include <stdint.h>

// Problem constants (B,T,H,A) = (64, 2048, 1024, 256)
#define BB 64
#define TT 2048
#define HH 1024
#define AA 256
#define BT (BB*TT)          // 131072 rows
#define NCTA (BT/M_CTA)     // 1024 CTAs, 16 per batch
#define CPB2 32             // S-partials per batch (2 halves x 16 CTAs)

#define M_CTA 128
#define KSTEP 32
#define NK (HH/KSTEP)       // 32
#define A_STRIDE 40         // halfs per A row (pad: 80B, conflict-free LDSM)
#define B_STRIDE 264        // halfs per B row (pad: 528B, conflict-free LDSM)
#define A_TILE (M_CTA*A_STRIDE)   // 5120 halfs / stage
#define B_TILE (KSTEP*B_STRIDE)   // 8448 halfs / stage

// ---------------- device scratch (no allocations allowed) ----------------
__device__ float g_S[(size_t)2 * NCTA * HH];   // per-half-chunk weighted sums (8MB)
__device__ float g_m[2 * NCTA];                // per-half-chunk max
__device__ float g_l[2 * NCTA];                // per-half-chunk exp-sum
__device__ __align__(16) __half g_Wh[HH * AA]; // W in fp16 [H][A]

__device__ __forceinline__ uint32_t smem_u32(const void* p) {
    uint32_t a;
    asm("{ .reg .u64 t; cvta.to.shared.u64 t, %1; cvt.u32.u64 %0, t; }" : "=r"(a) : "l"(p));
    return a;
}

// =====================================================================
// K0: convert W [H,A] fp32 -> g_Wh fp16 (rn)
// =====================================================================
__global__ void convert_w_kernel(const float* __restrict__ W)
{
    const int i = (blockIdx.x * 256 + threadIdx.x) * 4;
    const float4 f = *reinterpret_cast<const float4*>(W + i);
    __half2 h0 = __floats2half2_rn(f.x, f.y);
    __half2 h1 = __floats2half2_rn(f.z, f.w);
    *reinterpret_cast<uint2*>(g_Wh + i) =
        make_uint2(*reinterpret_cast<uint32_t*>(&h0), *reinterpret_cast<uint32_t*>(&h1));
}

// =====================================================================
// K1: fp16 mma.m16n8k16 GEMM (128x256 CTA tile, K double-buffered,
//     R10 structure with ONE sync per k-step: compute(cur); sts(nxt); sync)
//     + fused chunked-softmax epilogue with float4 S-pass (R10).
// 512 threads = 16 warps (4x4); warp tile 32 rows x 64 cols.
// =====================================================================
__global__ __launch_bounds__(512, 1)
void vu_fp16_kernel(const float* __restrict__ x,
                    const float* __restrict__ bo, const float* __restrict__ uo)
{
    extern __shared__ char smem[];
    __half* As = reinterpret_cast<__half*>(smem);                    // [2][A_TILE]
    __half* Bs = reinterpret_cast<__half*>(smem) + 2 * A_TILE;       // [2][B_TILE]
    __shared__ float vu_s[M_CTA];
    __shared__ float redm;

    const int tid  = threadIdx.x;
    const int lane = tid & 31;
    const int warp = tid >> 5;
    const int g    = lane >> 2;           // groupID
    const int tg   = lane & 3;            // thread-in-group
    const int wrow = (warp >> 2) * 32;    // 0,32,64,96
    const int wcol = (warp & 3) * 64;     // 0,64,128,192

    const uint32_t asBase = smem_u32(As);
    const uint32_t bsBase = smem_u32(Bs);

    const size_t row0 = (size_t)blockIdx.x * M_CTA;

    // ---- gmem staging mapping ----
    const int ar = tid >> 2;              // A row 0..127
    const int ak = (tid & 3) * 8;         // A k-sub 0,8,16,24
    const float* aPtr = x + (row0 + ar) * HH + ak;

    const int bk = tid >> 4;              // B k-row 0..31
    const int bn = (tid & 15) * 16;       // B n 0..240
    const __half* bPtr = g_Wh + (size_t)bk * AA + bn;

    float acc[2][8][4];
    #pragma unroll
    for (int mi = 0; mi < 2; mi++)
        #pragma unroll
        for (int ni = 0; ni < 8; ni++)
            #pragma unroll
            for (int c = 0; c < 4; c++) acc[mi][ni][c] = 0.f;

    __half2 aR[4];
    uint4 bR0, bR1;

    auto ldgA = [&](int k0) {
        const float4 f0 = *reinterpret_cast<const float4*>(aPtr + k0);
        const float4 f1 = *reinterpret_cast<const float4*>(aPtr + k0 + 4);
        aR[0] = __floats2half2_rn(f0.x, f0.y);
        aR[1] = __floats2half2_rn(f0.z, f0.w);
        aR[2] = __floats2half2_rn(f1.x, f1.y);
        aR[3] = __floats2half2_rn(f1.z, f1.w);
    };
    auto ldgB = [&](int k0) {
        const uint4* p = reinterpret_cast<const uint4*>(bPtr + (size_t)k0 * AA);
        bR0 = p[0];
        bR1 = p[1];
    };
    auto stsAB = [&](int st) {
        *reinterpret_cast<uint4*>(As + st * A_TILE + ar * A_STRIDE + ak) =
            *reinterpret_cast<uint4*>(aR);
        uint4* bq = reinterpret_cast<uint4*>(Bs + st * B_TILE + bk * B_STRIDE + bn);
        bq[0] = bR0;
        bq[1] = bR1;
    };

    auto compute = [&](int st) {
        const uint32_t aB = asBase + st * (A_TILE * 2);
        const uint32_t bB = bsBase + st * (B_TILE * 2);
        #pragma unroll
        for (int sub = 0; sub < 2; sub++) {
            uint32_t a[2][4];
            #pragma unroll
            for (int mi = 0; mi < 2; mi++) {
                const uint32_t addr = aB +
                    ((wrow + mi * 16 + (lane & 15)) * A_STRIDE
                     + sub * 16 + (lane >> 4) * 8) * 2;
                asm volatile("ldmatrix.sync.aligned.m8n8.x4.shared.b16 "
                             "{%0,%1,%2,%3}, [%4];"
                             : "=r"(a[mi][0]), "=r"(a[mi][1]),
                               "=r"(a[mi][2]), "=r"(a[mi][3]) : "r"(addr));
            }
            uint32_t b[4][4];
            #pragma unroll
            for (int nb = 0; nb < 4; nb++) {
                const uint32_t addr = bB +
                    ((sub * 16 + (lane & 15)) * B_STRIDE
                     + wcol + nb * 16 + (lane >> 4) * 8) * 2;
                asm volatile("ldmatrix.sync.aligned.m8n8.x4.trans.shared.b16 "
                             "{%0,%1,%2,%3}, [%4];"
                             : "=r"(b[nb][0]), "=r"(b[nb][1]),
                               "=r"(b[nb][2]), "=r"(b[nb][3]) : "r"(addr));
            }
            #pragma unroll
            for (int mi = 0; mi < 2; mi++)
                #pragma unroll
                for (int nb = 0; nb < 4; nb++) {
                    asm volatile(
                        "mma.sync.aligned.m16n8k16.row.col.f32.f16.f16.f32 "
                        "{%0,%1,%2,%3},{%4,%5,%6,%7},{%8,%9},{%0,%1,%2,%3};"
                        : "+f"(acc[mi][nb*2][0]), "+f"(acc[mi][nb*2][1]),
                          "+f"(acc[mi][nb*2][2]), "+f"(acc[mi][nb*2][3])
                        : "r"(a[mi][0]), "r"(a[mi][1]), "r"(a[mi][2]), "r"(a[mi][3]),
                          "r"(b[nb][0]), "r"(b[nb][1]));
                    asm volatile(
                        "mma.sync.aligned.m16n8k16.row.col.f32.f16.f16.f32 "
                        "{%0,%1,%2,%3},{%4,%5,%6,%7},{%8,%9},{%0,%1,%2,%3};"
                        : "+f"(acc[mi][nb*2+1][0]), "+f"(acc[mi][nb*2+1][1]),
                          "+f"(acc[mi][nb*2+1][2]), "+f"(acc[mi][nb*2+1][3])
                        : "r"(a[mi][0]), "r"(a[mi][1]), "r"(a[mi][2]), "r"(a[mi][3]),
                          "r"(b[nb][2]), "r"(b[nb][3]));
                }
        }
    };

    // ---- pipeline: ONE sync per k-step (write buffer != read buffer) ----
    ldgA(0); ldgB(0);
    stsAB(0);
    __syncthreads();

    for (int ks = 0; ks < NK; ks++) {
        const int cur = ks & 1;
        const bool more = (ks + 1 < NK);
        if (more) { ldgA((ks + 1) * KSTEP); ldgB((ks + 1) * KSTEP); }
        compute(cur);
        if (more) stsAB(cur ^ 1);
        __syncthreads();
    }

    // ---- epilogue 1: vu[row] = sum_a tanh(z + b[a]) * u[a] -> vu_s ----
    if (tid < M_CTA) vu_s[tid] = 0.f;
    __syncthreads();
    #pragma unroll
    for (int mi = 0; mi < 2; mi++) {
        float s0 = 0.f, s1 = 0.f;
        #pragma unroll
        for (int ni = 0; ni < 8; ni++) {
            const int c0 = wcol + ni * 8 + 2 * tg;
            const float b0v = bo[c0], b1v = bo[c0 + 1];
            const float u0v = uo[c0], u1v = uo[c0 + 1];
            s0 += tanhf(acc[mi][ni][0] + b0v) * u0v + tanhf(acc[mi][ni][1] + b1v) * u1v;
            s1 += tanhf(acc[mi][ni][2] + b0v) * u0v + tanhf(acc[mi][ni][3] + b1v) * u1v;
        }
        s0 += __shfl_xor_sync(0xffffffffu, s0, 1);
        s0 += __shfl_xor_sync(0xffffffffu, s0, 2);
        s1 += __shfl_xor_sync(0xffffffffu, s1, 1);
        s1 += __shfl_xor_sync(0xffffffffu, s1, 2);
        if (tg == 0) {
            atomicAdd(&vu_s[wrow + mi * 16 + g],     s0);
            atomicAdd(&vu_s[wrow + mi * 16 + g + 8], s1);
        }
    }
    __syncthreads();

    // ---- epilogue 2: local softmax stats ----
    if (warp == 0) {
        float a = fmaxf(fmaxf(vu_s[lane], vu_s[lane + 32]),
                        fmaxf(vu_s[lane + 64], vu_s[lane + 96]));
        #pragma unroll
        for (int o = 16; o; o >>= 1) a = fmaxf(a, __shfl_xor_sync(0xffffffffu, a, o));
        if (lane == 0) redm = a;
    }
    __syncthreads();
    const float m = redm;
    if (tid < M_CTA) vu_s[tid] = expf(vu_s[tid] - m);   // vu_s now holds weights
    __syncthreads();
    if (warp == 0) {
        float a = vu_s[lane] + vu_s[lane + 32] + vu_s[lane + 64] + vu_s[lane + 96];
        #pragma unroll
        for (int o = 16; o; o >>= 1) a += __shfl_xor_sync(0xffffffffu, a, o);
        if (lane == 0) {
            g_m[2 * blockIdx.x]     = m;  g_l[2 * blockIdx.x]     = a;
            g_m[2 * blockIdx.x + 1] = m;  g_l[2 * blockIdx.x + 1] = 0.f;
        }
    }
    __syncthreads();

    // ---- epilogue 3: S-pass, float4, row-split halves (R10) ----
    const int half = warp >> 3;               // 0 or 1
    const int t256 = tid & 255;               // thread index within half
    const float* xr = x + (row0 + half * 64) * HH + t256 * 4;
    const float* wv = vu_s + half * 64;

    float4 s = make_float4(0.f, 0.f, 0.f, 0.f);
    #pragma unroll 8
    for (int r = 0; r < 64; r++) {
        const float w = wv[r];
        const float4 v = *reinterpret_cast<const float4*>(xr + (size_t)r * HH);
        s.x = fmaf(w, v.x, s.x);
        s.y = fmaf(w, v.y, s.y);
        s.z = fmaf(w, v.z, s.z);
        s.w = fmaf(w, v.w, s.w);
    }
    *(reinterpret_cast<float4*>(g_S + ((size_t)(2 * blockIdx.x + half)) * HH) + t256) = s;
}

// =====================================================================
// K2: combine 32 half-chunk partials per batch (exact softmax merge),
//     write out [B, H+1] with ones column. 64 CTAs x 256 threads.
// =====================================================================
__global__ __launch_bounds__(256)
void combine_kernel(float* __restrict__ out)
{
    const int b = blockIdx.x, tid = threadIdx.x;
    const int c0 = b * CPB2;
    __shared__ float sm[CPB2], sl[CPB2];
    if (tid < CPB2) { sm[tid] = g_m[c0 + tid]; sl[tid] = g_l[c0 + tid]; }
    __syncthreads();

    float M = -1e30f;
    #pragma unroll
    for (int c = 0; c < CPB2; c++) M = fmaxf(M, sm[c]);
    float ec[CPB2];
    float L = 0.f;
    #pragma unroll
    for (int c = 0; c < CPB2; c++) {
        ec[c] = expf(sm[c] - M);
        L += ec[c] * sl[c];
    }
    const float inv = 1.f / L;

    for (int h = tid; h < HH; h += 256) {
        float s = 0.f;
        #pragma unroll
        for (int c = 0; c < CPB2; c++)
            s += ec[c] * g_S[(size_t)(c0 + c) * HH + h];
        out[b * (HH + 1) + h] = s * inv;
    }
    if (tid == 0) out[b * (HH + 1) + HH] = 1.0f;
}

// ---------------------------------------------------------------------
extern "C" void kernel_launch(void* const* d_in, const int* in_sizes, int n_in,
                              void* d_out, int out_size)
{
    const float* x  = (const float*)d_in[0];   // [64,2048,1024]
    const float* W  = (const float*)d_in[1];   // [1024,256]
    const float* bo = (const float*)d_in[2];   // [256]
    const float* uo = (const float*)d_in[3];   // [256]
    float* out = (float*)d_out;                // [64,1025]

    const int DSMEM = (2 * A_TILE + 2 * B_TILE) * 2;   // 54272 bytes
    static bool attr_done = false;
    if (!attr_done) {
        cudaFuncSetAttribute(vu_fp16_kernel,
                             cudaFuncAttributeMaxDynamicSharedMemorySize, DSMEM);
        attr_done = true;
    }

    convert_w_kernel<<<(HH * AA) / (256 * 4), 256>>>(W);
    vu_fp16_kernel<<<NCTA, 512, DSMEM>>>(x, bo, uo);
    combine_kernel<<<BB, 256>>>(out);
}